// round 1
// baseline (speedup 1.0000x reference)
#include <cuda_runtime.h>
#include <math.h>
#include <stdio.h>

// ---------------- problem constants ----------------
#define Bn   32
#define Sn   16
#define Ln   64
#define En   300
#define Pn   100
#define Hn   256
#define Gn   1024          // 4H
#define DATT 612           // 2H + P
#define N1   (Bn*Sn)       // 512 word-level sequences
#define M1   (N1*Ln)       // 32768 word rows
#define DIN1 (En+Pn)       // 400

// ---------------- scratch (device globals; no cudaMalloc allowed) ----------
__device__ float d_x[M1*DIN1];            // [32768][400]
__device__ float d_gpre[2*M1*Gn];          // [2][512][64][1024]
__device__ float d_senout[M1*2*Hn];        // [512][64][512]
__device__ float d_z[M1*DATT];             // [32768][612]
__device__ float d_zw[M1*DATT];            // [32768][612]
__device__ float d_scores[M1];             // [32768]
__device__ float d_senvec[N1*2*Hn];        // [512][512]
__device__ float d_sx[N1*DATT];            // [512][612]
__device__ float d_gpre2[2*N1*Gn];         // [2][32][16][1024]
__device__ float d_docout[N1*2*Hn];        // [32][16][512]
__device__ float d_hT[2*Bn*Hn];            // [2][32][256]
__device__ float d_z2[N1*DATT];            // [512][612]
__device__ float d_zw2[N1*DATT];           // [512][612]
__device__ float d_scores2[N1];            // [512]
__device__ float d_docvec[Bn*2*Hn];        // [32][512]
__device__ float d_wWt[DATT*DATT];         // word_W transposed
__device__ float d_sWt[DATT*DATT];         // sent_W transposed

__device__ __forceinline__ float sigmoidf(float x) { return 1.0f / (1.0f + expf(-x)); }

// ---------------- gather: x = [emb[tok] | wpos_emb[wpos]] -------------------
__global__ void gather_x_kernel(const int* __restrict__ tok,
                                const int* __restrict__ wpos,
                                const float* __restrict__ emb,
                                const float* __restrict__ wpe)
{
    int idx = blockIdx.x * blockDim.x + threadIdx.x;
    if (idx >= M1 * DIN1) return;
    int d = idx % DIN1;
    int m = idx / DIN1;
    float v;
    if (d < En) v = emb[(size_t)tok[m] * En + d];
    else        v = wpe[(size_t)wpos[m] * Pn + (d - En)];
    d_x[idx] = v;
}

// ---------------- generic tiled GEMM: C[M,N] = A[M,K] * W[N,K]^T + bias -----
// Requires M % 64 == 0. Handles N,K edges.
#define BM 64
#define BN 64
#define BK 16
__global__ __launch_bounds__(256)
void gemm_tn_bias(const float* __restrict__ A,
                  const float* __restrict__ W,
                  const float* __restrict__ bias,
                  float* __restrict__ C,
                  int M, int N, int K)
{
    __shared__ float As[BK][BM + 4];
    __shared__ float Ws[BK][BN + 4];
    int tid = threadIdx.x;
    int tx = tid & 15, ty = tid >> 4;
    int m0 = blockIdx.y * BM, n0 = blockIdx.x * BN;
    float acc[4][4];
#pragma unroll
    for (int i = 0; i < 4; i++)
#pragma unroll
        for (int j = 0; j < 4; j++) acc[i][j] = 0.f;

    int lrow = tid >> 2;           // 0..63
    int lk4  = (tid & 3) * 4;      // 0,4,8,12

    for (int k0 = 0; k0 < K; k0 += BK) {
        // A tile
        {
            int gm = m0 + lrow, gk = k0 + lk4;
            float4 v = make_float4(0.f, 0.f, 0.f, 0.f);
            if (gk + 3 < K) {
                v = *(const float4*)&A[(size_t)gm * K + gk];
            } else {
                float t0=0.f,t1=0.f,t2=0.f,t3=0.f;
                if (gk+0 < K) t0 = A[(size_t)gm*K+gk+0];
                if (gk+1 < K) t1 = A[(size_t)gm*K+gk+1];
                if (gk+2 < K) t2 = A[(size_t)gm*K+gk+2];
                if (gk+3 < K) t3 = A[(size_t)gm*K+gk+3];
                v = make_float4(t0,t1,t2,t3);
            }
            As[lk4+0][lrow]=v.x; As[lk4+1][lrow]=v.y; As[lk4+2][lrow]=v.z; As[lk4+3][lrow]=v.w;
        }
        // W tile
        {
            int gn = n0 + lrow, gk = k0 + lk4;
            float4 v = make_float4(0.f, 0.f, 0.f, 0.f);
            if (gn < N) {
                if (gk + 3 < K) {
                    v = *(const float4*)&W[(size_t)gn * K + gk];
                } else {
                    float t0=0.f,t1=0.f,t2=0.f,t3=0.f;
                    if (gk+0 < K) t0 = W[(size_t)gn*K+gk+0];
                    if (gk+1 < K) t1 = W[(size_t)gn*K+gk+1];
                    if (gk+2 < K) t2 = W[(size_t)gn*K+gk+2];
                    if (gk+3 < K) t3 = W[(size_t)gn*K+gk+3];
                    v = make_float4(t0,t1,t2,t3);
                }
            }
            Ws[lk4+0][lrow]=v.x; Ws[lk4+1][lrow]=v.y; Ws[lk4+2][lrow]=v.z; Ws[lk4+3][lrow]=v.w;
        }
        __syncthreads();
#pragma unroll
        for (int kk = 0; kk < BK; kk++) {
            float4 av = *(const float4*)&As[kk][ty*4];
            float4 bv = *(const float4*)&Ws[kk][tx*4];
            float a[4] = {av.x, av.y, av.z, av.w};
            float b[4] = {bv.x, bv.y, bv.z, bv.w};
#pragma unroll
            for (int i = 0; i < 4; i++)
#pragma unroll
                for (int j = 0; j < 4; j++) acc[i][j] += a[i] * b[j];
        }
        __syncthreads();
    }
#pragma unroll
    for (int i = 0; i < 4; i++) {
        int gm = m0 + ty*4 + i;
#pragma unroll
        for (int j = 0; j < 4; j++) {
            int gn = n0 + tx*4 + j;
            if (gn < N) C[(size_t)gm * N + gn] = acc[i][j] + bias[gn];
        }
    }
}

// ---------------- fused BiLSTM scan (both directions in one launch) --------
// gpre: [2][N][T][1024] (bias already added). Whh: [1024][256].
// out:  [N][T][ostride], fwd at col 0, bwd at col 256.
// Thread j owns gate columns {j, j+256, j+512, j+768} -> its own h column.
template<int ROWS>
__global__ __launch_bounds__(256)
void lstm_scan_kernel(const float* __restrict__ gpre,
                      const float* __restrict__ Whh_f,
                      const float* __restrict__ Whh_b,
                      float* __restrict__ out,
                      float* __restrict__ hT,
                      int N, int T, int ostride)
{
    __shared__ float hs[ROWS][256];
    __shared__ float ws[8][1032];
    int tid = threadIdx.x;
    int nb  = N / ROWS;
    int dir = blockIdx.x / nb;
    int n0  = (blockIdx.x % nb) * ROWS;
    const float* __restrict__ W = dir ? Whh_b : Whh_f;

    float c[ROWS];
#pragma unroll
    for (int r = 0; r < ROWS; r++) { c[r] = 0.f; hs[r][tid] = 0.f; }
    __syncthreads();

    for (int step = 0; step < T; step++) {
        int tt = dir ? (T - 1 - step) : step;
        float acc[ROWS][4];
#pragma unroll
        for (int r = 0; r < ROWS; r++) {
            size_t base = ((size_t)(dir * N + n0 + r) * T + tt) * Gn;
#pragma unroll
            for (int g = 0; g < 4; g++) acc[r][g] = gpre[base + g * 256 + tid];
        }
        for (int k0 = 0; k0 < 256; k0 += 8) {
            __syncthreads();
#pragma unroll
            for (int i = 0; i < 8; i++) {
                int idx  = tid + 256 * i;     // float4 slots over [1024 rows][2 parts]
                int row  = idx >> 1;
                int part = idx & 1;
                float4 v = *(const float4*)&W[row * 256 + k0 + part * 4];
                ws[part*4+0][row] = v.x; ws[part*4+1][row] = v.y;
                ws[part*4+2][row] = v.z; ws[part*4+3][row] = v.w;
            }
            __syncthreads();
#pragma unroll
            for (int kk = 0; kk < 8; kk++) {
                float w0 = ws[kk][tid];
                float w1 = ws[kk][256 + tid];
                float w2 = ws[kk][512 + tid];
                float w3 = ws[kk][768 + tid];
#pragma unroll
                for (int r = 0; r < ROWS; r++) {
                    float hv = hs[r][k0 + kk];
                    acc[r][0] += hv * w0;
                    acc[r][1] += hv * w1;
                    acc[r][2] += hv * w2;
                    acc[r][3] += hv * w3;
                }
            }
        }
        __syncthreads();   // all hs reads for this step complete
#pragma unroll
        for (int r = 0; r < ROWS; r++) {
            float iv = sigmoidf(acc[r][0]);
            float fv = sigmoidf(acc[r][1]);
            float gv = tanhf(acc[r][2]);
            float ov = sigmoidf(acc[r][3]);
            c[r] = fv * c[r] + iv * gv;
            float h = ov * tanhf(c[r]);
            hs[r][tid] = h;
            out[((size_t)(n0 + r) * T + tt) * ostride + dir * 256 + tid] = h;
            if (hT != nullptr && step == T - 1)
                hT[((size_t)dir * N + n0 + r) * 256 + tid] = h;
        }
    }
}

// ---------------- word-attention helpers -----------------------------------
__global__ void build_z_kernel() // z = [senout(512) | x[:,300:400]]
{
    int idx = blockIdx.x * blockDim.x + threadIdx.x;
    if (idx >= M1 * DATT) return;
    int d = idx % DATT, m = idx / DATT;
    d_z[idx] = (d < 2*Hn) ? d_senout[(size_t)m * (2*Hn) + d]
                          : d_x[(size_t)m * DIN1 + En + (d - 2*Hn)];
}

__global__ void transpose_datt(const float* __restrict__ W, float* __restrict__ Wt)
{
    int idx = blockIdx.x * blockDim.x + threadIdx.x;
    if (idx >= DATT * DATT) return;
    int e = idx % DATT, d = idx / DATT;
    Wt[(size_t)e * DATT + d] = W[idx];
}

// scores[row] = sum_d tanh(zw[row][d] + bias[d]) * proj[d];  one warp per row
__global__ void attn_score_kernel(const float* __restrict__ zw,
                                  const float* __restrict__ bias,
                                  const float* __restrict__ proj,
                                  float* __restrict__ sc, int M)
{
    int gwarp = (blockIdx.x * blockDim.x + threadIdx.x) >> 5;
    int lane  = threadIdx.x & 31;
    if (gwarp >= M) return;
    const float* row = zw + (size_t)gwarp * DATT;
    float s = 0.f;
    for (int d = lane; d < DATT; d += 32) s += tanhf(row[d] + bias[d]) * proj[d];
#pragma unroll
    for (int o = 16; o > 0; o >>= 1) s += __shfl_xor_sync(0xffffffffu, s, o);
    if (lane == 0) sc[gwarp] = s;
}

// softmax over T then pool h: outv[n][col] = sum_t a[t]*hsrc[n][t][col]
__global__ void softmax_pool_kernel(const float* __restrict__ sc,
                                    const float* __restrict__ hsrc,
                                    float* __restrict__ outv,
                                    int T, int stride)
{
    __shared__ float a[64];
    __shared__ float inv_s;
    int n = blockIdx.x, tid = threadIdx.x;
    if (tid == 0) {
        float mx = -1e30f;
        for (int t = 0; t < T; t++) mx = fmaxf(mx, sc[n * T + t]);
        float sum = 0.f;
        for (int t = 0; t < T; t++) { float e = expf(sc[n * T + t] - mx); a[t] = e; sum += e; }
        inv_s = 1.f / sum;
    }
    __syncthreads();
    float inv = inv_s;
    for (int col = tid; col < 2*Hn; col += blockDim.x) {
        float acc = 0.f;
        for (int t = 0; t < T; t++)
            acc += a[t] * hsrc[((size_t)n * T + t) * stride + col];
        outv[(size_t)n * (2*Hn) + col] = acc * inv;
    }
}

// ---------------- sentence-level glue ---------------------------------------
__global__ void build_sx_kernel(const int* __restrict__ seg,
                                const float* __restrict__ spe)
{
    int idx = blockIdx.x * blockDim.x + threadIdx.x;
    if (idx >= N1 * DATT) return;
    int d = idx % DATT, m = idx / DATT;
    d_sx[idx] = (d < 2*Hn) ? d_senvec[(size_t)m * (2*Hn) + d]
                           : spe[(size_t)seg[m] * Pn + (d - 2*Hn)];
}

__global__ void build_z2_kernel(const int* __restrict__ seg,
                                const float* __restrict__ spe)
{
    int idx = blockIdx.x * blockDim.x + threadIdx.x;
    if (idx >= N1 * DATT) return;
    int d = idx % DATT, m = idx / DATT;
    d_z2[idx] = (d < 2*Hn) ? d_docout[(size_t)m * (2*Hn) + d]
                           : spe[(size_t)seg[m] * Pn + (d - 2*Hn)];
}

// ---------------- final dense: out[b][p] = feats . dense_W[p] + b -----------
__global__ void final_dense_kernel(const float* __restrict__ dW,
                                   const float* __restrict__ db,
                                   float* __restrict__ outp)
{
    __shared__ float r0[128], r1[128], r2[128];
    int b = blockIdx.x, tid = threadIdx.x;
    float a0 = 0.f, a1 = 0.f, a2 = 0.f;
    for (int k = tid; k < 4*Hn; k += 128) {
        float f;
        if (k < 2*Hn)        f = d_docvec[b * 2*Hn + k];
        else if (k < 3*Hn)   f = d_hT[(0 * Bn + b) * Hn + (k - 2*Hn)];
        else                 f = d_hT[(1 * Bn + b) * Hn + (k - 3*Hn)];
        a0 += f * dW[0*4*Hn + k];
        a1 += f * dW[1*4*Hn + k];
        a2 += f * dW[2*4*Hn + k];
    }
    r0[tid] = a0; r1[tid] = a1; r2[tid] = a2;
    __syncthreads();
    for (int s = 64; s > 0; s >>= 1) {
        if (tid < s) { r0[tid] += r0[tid+s]; r1[tid] += r1[tid+s]; r2[tid] += r2[tid+s]; }
        __syncthreads();
    }
    if (tid == 0) {
        outp[b*3+0] = r0[0] + db[0];
        outp[b*3+1] = r1[0] + db[1];
        outp[b*3+2] = r2[0] + db[2];
    }
}

// ---------------- host driver ----------------------------------------------
extern "C" void kernel_launch(void* const* d_in, const int* in_sizes, int n_in,
                              void* d_out, int out_size)
{
    const int*   tok     = (const int*)d_in[0];
    const int*   wpos    = (const int*)d_in[1];
    const int*   seg     = (const int*)d_in[2];
    const float* emb     = (const float*)d_in[3];
    const float* wpe     = (const float*)d_in[4];
    const float* spe     = (const float*)d_in[5];
    const float* wWih_f  = (const float*)d_in[6];
    const float* wWhh_f  = (const float*)d_in[7];
    const float* wb_f    = (const float*)d_in[8];
    const float* wWih_b  = (const float*)d_in[9];
    const float* wWhh_b  = (const float*)d_in[10];
    const float* wb_b    = (const float*)d_in[11];
    const float* sWih_f  = (const float*)d_in[12];
    const float* sWhh_f  = (const float*)d_in[13];
    const float* sb_f    = (const float*)d_in[14];
    const float* sWih_b  = (const float*)d_in[15];
    const float* sWhh_b  = (const float*)d_in[16];
    const float* sb_b    = (const float*)d_in[17];
    const float* word_W  = (const float*)d_in[18];
    const float* word_b  = (const float*)d_in[19];
    const float* word_p  = (const float*)d_in[20];
    const float* sent_W  = (const float*)d_in[21];
    const float* sent_b  = (const float*)d_in[22];
    const float* sent_p  = (const float*)d_in[23];
    const float* dense_W = (const float*)d_in[24];
    const float* dense_b = (const float*)d_in[25];
    float* outp = (float*)d_out;

    float *px, *pgpre, *psenout, *pz, *pzw, *psc, *psenvec, *psx, *pgpre2,
          *pdocout, *phT, *pz2, *pzw2, *psc2, *pdocvec, *pwWt, *psWt;
    cudaGetSymbolAddress((void**)&px,      d_x);
    cudaGetSymbolAddress((void**)&pgpre,   d_gpre);
    cudaGetSymbolAddress((void**)&psenout, d_senout);
    cudaGetSymbolAddress((void**)&pz,      d_z);
    cudaGetSymbolAddress((void**)&pzw,     d_zw);
    cudaGetSymbolAddress((void**)&psc,     d_scores);
    cudaGetSymbolAddress((void**)&psenvec, d_senvec);
    cudaGetSymbolAddress((void**)&psx,     d_sx);
    cudaGetSymbolAddress((void**)&pgpre2,  d_gpre2);
    cudaGetSymbolAddress((void**)&pdocout, d_docout);
    cudaGetSymbolAddress((void**)&phT,     d_hT);
    cudaGetSymbolAddress((void**)&pz2,     d_z2);
    cudaGetSymbolAddress((void**)&pzw2,    d_zw2);
    cudaGetSymbolAddress((void**)&psc2,    d_scores2);
    cudaGetSymbolAddress((void**)&pdocvec, d_docvec);
    cudaGetSymbolAddress((void**)&pwWt,    d_wWt);
    cudaGetSymbolAddress((void**)&psWt,    d_sWt);

    // 1. embedding/position gather -> x [32768,400]
    gather_x_kernel<<<(M1*DIN1 + 255)/256, 256>>>(tok, wpos, emb, wpe);

    // 2. word-level input GEMMs (g_pre includes bias)
    {
        dim3 g(Gn/BN, M1/BM);
        gemm_tn_bias<<<g, 256>>>(px, wWih_f, wb_f, pgpre,              M1, Gn, DIN1);
        gemm_tn_bias<<<g, 256>>>(px, wWih_b, wb_b, pgpre + (size_t)M1*Gn, M1, Gn, DIN1);
    }

    // 3. word-level BiLSTM scan (both dirs in one launch)
    lstm_scan_kernel<8><<<2*(N1/8), 256>>>(pgpre, wWhh_f, wWhh_b, psenout,
                                           (float*)nullptr, N1, Ln, 2*Hn);

    // 4. word attention
    build_z_kernel<<<(M1*DATT + 255)/256, 256>>>();
    transpose_datt<<<(DATT*DATT + 255)/256, 256>>>(word_W, pwWt);
    {
        dim3 g((DATT + BN - 1)/BN, M1/BM);
        gemm_tn_bias<<<g, 256>>>(pz, pwWt, word_b, pzw, M1, DATT, DATT);
    }
    attn_score_kernel<<<(M1*32 + 255)/256, 256>>>(pzw, word_b, word_p, psc, M1);
    softmax_pool_kernel<<<N1, 256>>>(psc, psenout, psenvec, Ln, 2*Hn);

    // 5. sentence-level input
    build_sx_kernel<<<(N1*DATT + 255)/256, 256>>>(seg, spe);
    {
        dim3 g(Gn/BN, N1/BM);
        gemm_tn_bias<<<g, 256>>>(psx, sWih_f, sb_f, pgpre2,               N1, Gn, DATT);
        gemm_tn_bias<<<g, 256>>>(psx, sWih_b, sb_b, pgpre2 + (size_t)N1*Gn, N1, Gn, DATT);
    }

    // 6. sentence BiLSTM scan (keeps final hidden states)
    lstm_scan_kernel<1><<<2*Bn, 256>>>(pgpre2, sWhh_f, sWhh_b, pdocout,
                                       phT, Bn, Sn, 2*Hn);

    // 7. sentence attention
    build_z2_kernel<<<(N1*DATT + 255)/256, 256>>>(seg, spe);
    transpose_datt<<<(DATT*DATT + 255)/256, 256>>>(sent_W, psWt);
    {
        dim3 g((DATT + BN - 1)/BN, N1/BM);
        gemm_tn_bias<<<g, 256>>>(pz2, psWt, sent_b, pzw2, N1, DATT, DATT);
    }
    attn_score_kernel<<<(N1*32 + 255)/256, 256>>>(pzw2, sent_b, sent_p, psc2, N1);
    softmax_pool_kernel<<<Bn, 256>>>(psc2, pdocout, pdocvec, Sn, 2*Hn);

    // 8. classifier head
    final_dense_kernel<<<Bn, 128>>>(dense_W, dense_b, outp);
}

// round 2
// speedup vs baseline: 1.4926x; 1.4926x over previous
#include <cuda_runtime.h>
#include <math.h>

// ---------------- problem constants ----------------
#define Bn   32
#define Sn   16
#define Ln   64
#define En   300
#define Pn   100
#define Hn   256
#define Gn   1024          // 4H
#define DATT 612           // 2H + P
#define N1   (Bn*Sn)       // 512 word-level sequences
#define M1   (N1*Ln)       // 32768 word rows
#define DIN1 (En+Pn)       // 400
#define NBATT 5            // ceil(612/128)

typedef unsigned long long u64;

// ---------------- scratch (device globals) ----------------------------------
__device__ float d_x[M1*DIN1];        // [32768][400]
__device__ float d_gpre[2*M1*Gn];     // [2][32768][1024]
__device__ float d_z[M1*DATT];        // [32768][612] : scan out (0..511) | wpe (512..611)
__device__ float d_scp[M1*NBATT];
__device__ float d_scores[M1];
__device__ float d_senvec[N1*2*Hn];
__device__ float d_sx[N1*DATT];
__device__ float d_gpre2[2*N1*Gn];
__device__ float d_z2[N1*DATT];       // [512][612] : doc scan out | spe
__device__ float d_hT[2*Bn*Hn];
__device__ float d_scp2[N1*NBATT];
__device__ float d_scores2[N1];
__device__ float d_docvec[Bn*2*Hn];
__device__ float d_wWt[DATT*DATT];    // word_W transposed [e][d]
__device__ float d_sWt[DATT*DATT];
__device__ float d_wtf[Hn*Gn];        // word Whh_f transposed [k][g]
__device__ float d_wtb[Hn*Gn];
__device__ float d_stf[Hn*Gn];
__device__ float d_stb[Hn*Gn];

__device__ __forceinline__ float sigmoidf(float x) { return 1.0f / (1.0f + expf(-x)); }

__device__ __forceinline__ void fma2(u64& d, u64 a, u64 b) {
    asm("fma.rn.f32x2 %0, %1, %2, %3;" : "=l"(d) : "l"(a), "l"(b), "l"(d));
}
__device__ __forceinline__ u64 pack2(float x, float y) {
    u64 r; asm("mov.b64 %0, {%1,%2};" : "=l"(r) : "f"(x), "f"(y)); return r;
}
__device__ __forceinline__ void unpack2(float& lo, float& hi, u64 v) {
    asm("mov.b64 {%0,%1}, %2;" : "=f"(lo), "=f"(hi) : "l"(v));
}

// ---------------- gather: x = [emb|wpe]; also z pos columns ------------------
__global__ void gather_x_kernel(const int* __restrict__ tok,
                                const int* __restrict__ wpos,
                                const float* __restrict__ emb,
                                const float* __restrict__ wpe)
{
    int idx = blockIdx.x * blockDim.x + threadIdx.x;
    if (idx >= M1 * DIN1) return;
    int d = idx % DIN1;
    int m = idx / DIN1;
    float v;
    if (d < En) v = emb[(size_t)tok[m] * En + d];
    else {
        v = wpe[(size_t)wpos[m] * Pn + (d - En)];
        d_z[(size_t)m * DATT + 2*Hn + (d - En)] = v;   // z position slice
    }
    d_x[idx] = v;
}

// ---------------- generic transpose: Wt[k*Gr + g] = W[g*Kc + k] --------------
__global__ void transpose_k(const float* __restrict__ W, float* __restrict__ Wt,
                            int Gr, int Kc)
{
    int idx = blockIdx.x * blockDim.x + threadIdx.x;
    if (idx >= Gr * Kc) return;
    int g = idx / Kc, k = idx % Kc;
    Wt[(size_t)k * Gr + g] = W[idx];
}

// ---------------- 128x128x16 f32x2 GEMM: C = A[M,K] @ W[N,K]^T (+bias) -------
// ATTN=true: fused tanh(.+bias)*proj row-reduction -> C[m*gridDim.x + bx]
#define GBK 16
__device__ __forceinline__ float4 ldg4g(const float* __restrict__ rowp, int k, int K) {
    if (k + 3 < K) return *(const float4*)(rowp + k);
    float4 v = make_float4(0.f, 0.f, 0.f, 0.f);
    if (k     < K) v.x = rowp[k];
    if (k + 1 < K) v.y = rowp[k+1];
    if (k + 2 < K) v.z = rowp[k+2];
    return v;
}

template<bool ATTN>
__global__ __launch_bounds__(256, 1)
void gemm_f2(const float* __restrict__ A, const float* __restrict__ W,
             const float* __restrict__ bias, const float* __restrict__ proj,
             float* __restrict__ C, int M, int N, int K)
{
    __shared__ float As[2][GBK][128];
    __shared__ float Bs[2][GBK][128];
    __shared__ float red[128][17];
    const int tid = threadIdx.x;
    const int tx = tid & 15, ty = tid >> 4;
    const int m0 = blockIdx.y * 128, n0 = blockIdx.x * 128;
    const int lr = tid >> 1;
    const int lk = (tid & 1) * 8;
    const int nk = (K + GBK - 1) / GBK;

    const float* __restrict__ pa = &A[(size_t)(m0 + lr) * K];
    const bool nok = (n0 + lr) < N;
    const float* __restrict__ pb = &W[(size_t)(n0 + lr) * K];

    u64 acc2[4][8];
#pragma unroll
    for (int i = 0; i < 4; i++)
#pragma unroll
        for (int j = 0; j < 8; j++) acc2[i][j] = 0ULL;

    // load tile 0
#pragma unroll
    for (int h = 0; h < 2; h++) {
        int k = lk + h * 4;
        float4 va = ldg4g(pa, k, K);
        As[0][k+0][lr] = va.x; As[0][k+1][lr] = va.y;
        As[0][k+2][lr] = va.z; As[0][k+3][lr] = va.w;
        float4 vb = nok ? ldg4g(pb, k, K) : make_float4(0.f,0.f,0.f,0.f);
        Bs[0][k+0][lr] = vb.x; Bs[0][k+1][lr] = vb.y;
        Bs[0][k+2][lr] = vb.z; Bs[0][k+3][lr] = vb.w;
    }
    __syncthreads();

    for (int kt = 0; kt < nk; kt++) {
        const int cur = kt & 1;
        float4 pA[2], pB[2];
        if (kt + 1 < nk) {
            int kb = (kt + 1) * GBK + lk;
#pragma unroll
            for (int h = 0; h < 2; h++) {
                pA[h] = ldg4g(pa, kb + h*4, K);
                pB[h] = nok ? ldg4g(pb, kb + h*4, K) : make_float4(0.f,0.f,0.f,0.f);
            }
        }
#pragma unroll
        for (int kk = 0; kk < GBK; kk++) {
            u64 a2[4];
#pragma unroll
            for (int mp = 0; mp < 4; mp++)
                a2[mp] = *(const u64*)&As[cur][kk][ty*8 + mp*2];
            float4 b0 = *(const float4*)&Bs[cur][kk][tx*8];
            float4 b1 = *(const float4*)&Bs[cur][kk][tx*8 + 4];
            u64 bd[8];
            bd[0]=pack2(b0.x,b0.x); bd[1]=pack2(b0.y,b0.y);
            bd[2]=pack2(b0.z,b0.z); bd[3]=pack2(b0.w,b0.w);
            bd[4]=pack2(b1.x,b1.x); bd[5]=pack2(b1.y,b1.y);
            bd[6]=pack2(b1.z,b1.z); bd[7]=pack2(b1.w,b1.w);
#pragma unroll
            for (int mp = 0; mp < 4; mp++)
#pragma unroll
                for (int j = 0; j < 8; j++) fma2(acc2[mp][j], a2[mp], bd[j]);
        }
        if (kt + 1 < nk) {
            int nb = cur ^ 1;
#pragma unroll
            for (int h = 0; h < 2; h++) {
                int k = lk + h * 4;
                As[nb][k+0][lr] = pA[h].x; As[nb][k+1][lr] = pA[h].y;
                As[nb][k+2][lr] = pA[h].z; As[nb][k+3][lr] = pA[h].w;
                Bs[nb][k+0][lr] = pB[h].x; Bs[nb][k+1][lr] = pB[h].y;
                Bs[nb][k+2][lr] = pB[h].z; Bs[nb][k+3][lr] = pB[h].w;
            }
        }
        __syncthreads();
    }

    if (!ATTN) {
        // N, M multiples of 128 for all non-fused uses
        float bv[8];
#pragma unroll
        for (int j = 0; j < 8; j++) bv[j] = bias[n0 + tx*8 + j];
#pragma unroll
        for (int mp = 0; mp < 4; mp++) {
            float lo[8], hi[8];
#pragma unroll
            for (int j = 0; j < 8; j++) unpack2(lo[j], hi[j], acc2[mp][j]);
            size_t r0 = (size_t)(m0 + ty*8 + mp*2) * N + n0 + tx*8;
            float4 o;
            o = make_float4(lo[0]+bv[0], lo[1]+bv[1], lo[2]+bv[2], lo[3]+bv[3]);
            *(float4*)&C[r0] = o;
            o = make_float4(lo[4]+bv[4], lo[5]+bv[5], lo[6]+bv[6], lo[7]+bv[7]);
            *(float4*)&C[r0 + 4] = o;
            o = make_float4(hi[0]+bv[0], hi[1]+bv[1], hi[2]+bv[2], hi[3]+bv[3]);
            *(float4*)&C[r0 + N] = o;
            o = make_float4(hi[4]+bv[4], hi[5]+bv[5], hi[6]+bv[6], hi[7]+bv[7]);
            *(float4*)&C[r0 + N + 4] = o;
        }
    } else {
        float rs[8];
#pragma unroll
        for (int i = 0; i < 8; i++) rs[i] = 0.f;
#pragma unroll
        for (int j = 0; j < 8; j++) {
            int n = n0 + tx*8 + j;
            if (n < N) {
                float bn = bias[n], pn = proj[n];
#pragma unroll
                for (int mp = 0; mp < 4; mp++) {
                    float lo, hi; unpack2(lo, hi, acc2[mp][j]);
                    rs[mp*2]     += tanhf(lo + bn) * pn;
                    rs[mp*2 + 1] += tanhf(hi + bn) * pn;
                }
            }
        }
#pragma unroll
        for (int i = 0; i < 8; i++) red[ty*8 + i][tx] = rs[i];
        __syncthreads();
        if (tid < 128) {
            float s = 0.f;
#pragma unroll
            for (int x = 0; x < 16; x++) s += red[tid][x];
            C[(size_t)(m0 + tid) * gridDim.x + blockIdx.x] = s;
        }
    }
}

// ---------------- BiLSTM scan: double-buffered W staging + f32x2 -------------
// gpre: [2][N][T][1024] (bias included). Wt: [256][1024] (k-major transposed).
// out: [N][T][ostride], fwd at col 0, bwd at col 256.
template<int ROWS>
__global__ __launch_bounds__(256, 1)
void lstm_scan2(const float* __restrict__ gpre,
                const float* __restrict__ Wt_f,
                const float* __restrict__ Wt_b,
                float* __restrict__ out,
                float* __restrict__ hT,
                int N, int T, int ostride)
{
    extern __shared__ float sm[];
    float* ws = sm;                 // [2][8][1024]
    float* hs = sm + 2*8*1024;      // [256][ROWS]
    const int tid = threadIdx.x;
    const int nb  = N / ROWS;
    const int dir = blockIdx.x / nb;
    const int n0  = (blockIdx.x % nb) * ROWS;
    const float* __restrict__ Wt = dir ? Wt_b : Wt_f;

    float c[ROWS];
#pragma unroll
    for (int r = 0; r < ROWS; r++) c[r] = 0.f;
    for (int i = tid; i < 256*ROWS; i += 256) hs[i] = 0.f;

    // preload W tile 0 (linear 32KB copy)
#pragma unroll
    for (int i = 0; i < 8; i++)
        *(float4*)&ws[(tid + 256*i)*4] = *(const float4*)&Wt[(tid + 256*i)*4];
    __syncthreads();

    const int NT = 32;  // 256 / 8
    for (int step = 0; step < T; step++) {
        const int tt = dir ? (T - 1 - step) : step;

        if (ROWS == 8) {
            u64 acc2[4][4];
#pragma unroll
            for (int rp = 0; rp < 4; rp++) {
                size_t b0 = ((size_t)(dir*N + n0 + rp*2    ) * T + tt) * Gn;
                size_t b1 = ((size_t)(dir*N + n0 + rp*2 + 1) * T + tt) * Gn;
#pragma unroll
                for (int g = 0; g < 4; g++)
                    acc2[rp][g] = pack2(gpre[b0 + g*256 + tid], gpre[b1 + g*256 + tid]);
            }
            for (int kt = 0; kt < NT; kt++) {
                const int cur = kt & 1;
                const bool last = (step == T-1) && (kt == NT-1);
                float4 pf[8];
                if (!last) {
                    const float* src = &Wt[(size_t)((kt + 1) & 31) * 8192];
#pragma unroll
                    for (int i = 0; i < 8; i++)
                        pf[i] = *(const float4*)&src[(tid + 256*i)*4];
                }
#pragma unroll
                for (int kk = 0; kk < 8; kk++) {
                    const int k = kt*8 + kk;
                    const float* wrow = &ws[(cur*8 + kk)*1024];
                    float w0 = wrow[tid], w1 = wrow[256+tid];
                    float w2 = wrow[512+tid], w3 = wrow[768+tid];
                    u64 wd0 = pack2(w0,w0), wd1 = pack2(w1,w1);
                    u64 wd2 = pack2(w2,w2), wd3 = pack2(w3,w3);
#pragma unroll
                    for (int rp = 0; rp < 4; rp++) {
                        u64 h2 = *(const u64*)&hs[k*8 + rp*2];
                        fma2(acc2[rp][0], h2, wd0);
                        fma2(acc2[rp][1], h2, wd1);
                        fma2(acc2[rp][2], h2, wd2);
                        fma2(acc2[rp][3], h2, wd3);
                    }
                }
                if (!last) {
                    float* dst = &ws[(cur ^ 1) * 8192];
#pragma unroll
                    for (int i = 0; i < 8; i++)
                        *(float4*)&dst[(tid + 256*i)*4] = pf[i];
                }
                __syncthreads();
            }
#pragma unroll
            for (int rp = 0; rp < 4; rp++) {
                float p[4][2];
#pragma unroll
                for (int g = 0; g < 4; g++) unpack2(p[g][0], p[g][1], acc2[rp][g]);
#pragma unroll
                for (int hh = 0; hh < 2; hh++) {
                    int r = rp*2 + hh;
                    float iv = sigmoidf(p[0][hh]);
                    float fv = sigmoidf(p[1][hh]);
                    float gv = tanhf(p[2][hh]);
                    float ov = sigmoidf(p[3][hh]);
                    c[r] = fv * c[r] + iv * gv;
                    float hv = ov * tanhf(c[r]);
                    hs[tid*8 + r] = hv;
                    out[((size_t)(n0 + r) * T + tt) * ostride + dir*256 + tid] = hv;
                }
            }
            __syncthreads();
        } else {
            // ROWS == 1
            float acc[4];
            size_t b0 = ((size_t)(dir*N + n0) * T + tt) * Gn;
#pragma unroll
            for (int g = 0; g < 4; g++) acc[g] = gpre[b0 + g*256 + tid];
            for (int kt = 0; kt < NT; kt++) {
                const int cur = kt & 1;
                const bool last = (step == T-1) && (kt == NT-1);
                float4 pf[8];
                if (!last) {
                    const float* src = &Wt[(size_t)((kt + 1) & 31) * 8192];
#pragma unroll
                    for (int i = 0; i < 8; i++)
                        pf[i] = *(const float4*)&src[(tid + 256*i)*4];
                }
#pragma unroll
                for (int kk = 0; kk < 8; kk++) {
                    const int k = kt*8 + kk;
                    const float* wrow = &ws[(cur*8 + kk)*1024];
                    float hv = hs[k];
                    acc[0] += hv * wrow[tid];
                    acc[1] += hv * wrow[256+tid];
                    acc[2] += hv * wrow[512+tid];
                    acc[3] += hv * wrow[768+tid];
                }
                if (!last) {
                    float* dst = &ws[(cur ^ 1) * 8192];
#pragma unroll
                    for (int i = 0; i < 8; i++)
                        *(float4*)&dst[(tid + 256*i)*4] = pf[i];
                }
                __syncthreads();
            }
            float iv = sigmoidf(acc[0]);
            float fv = sigmoidf(acc[1]);
            float gv = tanhf(acc[2]);
            float ov = sigmoidf(acc[3]);
            c[0] = fv * c[0] + iv * gv;
            float hv = ov * tanhf(c[0]);
            hs[tid] = hv;
            out[((size_t)n0 * T + tt) * ostride + dir*256 + tid] = hv;
            if (hT != nullptr && step == T-1)
                hT[((size_t)dir * N + n0) * 256 + tid] = hv;
            __syncthreads();
        }
    }
}

// ---------------- attention glue ---------------------------------------------
__global__ void sum_scores(const float* __restrict__ scp, float* __restrict__ sc,
                           int M, int NB)
{
    int m = blockIdx.x * blockDim.x + threadIdx.x;
    if (m >= M) return;
    float s = 0.f;
    for (int j = 0; j < NB; j++) s += scp[(size_t)m * NB + j];
    sc[m] = s;
}

__global__ void softmax_pool_kernel(const float* __restrict__ sc,
                                    const float* __restrict__ hsrc,
                                    float* __restrict__ outv,
                                    int T, int stride)
{
    __shared__ float a[64];
    __shared__ float inv_s;
    int n = blockIdx.x, tid = threadIdx.x;
    if (tid == 0) {
        float mx = -1e30f;
        for (int t = 0; t < T; t++) mx = fmaxf(mx, sc[n * T + t]);
        float sum = 0.f;
        for (int t = 0; t < T; t++) { float e = expf(sc[n * T + t] - mx); a[t] = e; sum += e; }
        inv_s = 1.f / sum;
    }
    __syncthreads();
    float inv = inv_s;
    for (int col = tid; col < 2*Hn; col += blockDim.x) {
        float acc = 0.f;
        for (int t = 0; t < T; t++)
            acc += a[t] * hsrc[((size_t)n * T + t) * stride + col];
        outv[(size_t)n * (2*Hn) + col] = acc * inv;
    }
}

__global__ void build_sx_kernel(const int* __restrict__ seg,
                                const float* __restrict__ spe)
{
    int idx = blockIdx.x * blockDim.x + threadIdx.x;
    if (idx >= N1 * DATT) return;
    int d = idx % DATT, m = idx / DATT;
    d_sx[idx] = (d < 2*Hn) ? d_senvec[(size_t)m * (2*Hn) + d]
                           : spe[(size_t)seg[m] * Pn + (d - 2*Hn)];
}

__global__ void fill_z2pos(const int* __restrict__ seg, const float* __restrict__ spe)
{
    int idx = blockIdx.x * blockDim.x + threadIdx.x;
    if (idx >= N1 * Pn) return;
    int m = idx / Pn, d = idx % Pn;
    d_z2[(size_t)m * DATT + 2*Hn + d] = spe[(size_t)seg[m] * Pn + d];
}

// ---------------- classifier head --------------------------------------------
__global__ void final_dense_kernel(const float* __restrict__ dW,
                                   const float* __restrict__ db,
                                   float* __restrict__ outp)
{
    __shared__ float r0[128], r1[128], r2[128];
    int b = blockIdx.x, tid = threadIdx.x;
    float a0 = 0.f, a1 = 0.f, a2 = 0.f;
    for (int k = tid; k < 4*Hn; k += 128) {
        float f;
        if (k < 2*Hn)        f = d_docvec[b * 2*Hn + k];
        else if (k < 3*Hn)   f = d_hT[(0 * Bn + b) * Hn + (k - 2*Hn)];
        else                 f = d_hT[(1 * Bn + b) * Hn + (k - 3*Hn)];
        a0 += f * dW[0*4*Hn + k];
        a1 += f * dW[1*4*Hn + k];
        a2 += f * dW[2*4*Hn + k];
    }
    r0[tid] = a0; r1[tid] = a1; r2[tid] = a2;
    __syncthreads();
    for (int s = 64; s > 0; s >>= 1) {
        if (tid < s) { r0[tid] += r0[tid+s]; r1[tid] += r1[tid+s]; r2[tid] += r2[tid+s]; }
        __syncthreads();
    }
    if (tid == 0) {
        outp[b*3+0] = r0[0] + db[0];
        outp[b*3+1] = r1[0] + db[1];
        outp[b*3+2] = r2[0] + db[2];
    }
}

// ---------------- host driver -------------------------------------------------
extern "C" void kernel_launch(void* const* d_in, const int* in_sizes, int n_in,
                              void* d_out, int out_size)
{
    const int*   tok     = (const int*)d_in[0];
    const int*   wpos    = (const int*)d_in[1];
    const int*   seg     = (const int*)d_in[2];
    const float* emb     = (const float*)d_in[3];
    const float* wpe     = (const float*)d_in[4];
    const float* spe     = (const float*)d_in[5];
    const float* wWih_f  = (const float*)d_in[6];
    const float* wWhh_f  = (const float*)d_in[7];
    const float* wb_f    = (const float*)d_in[8];
    const float* wWih_b  = (const float*)d_in[9];
    const float* wWhh_b  = (const float*)d_in[10];
    const float* wb_b    = (const float*)d_in[11];
    const float* sWih_f  = (const float*)d_in[12];
    const float* sWhh_f  = (const float*)d_in[13];
    const float* sb_f    = (const float*)d_in[14];
    const float* sWih_b  = (const float*)d_in[15];
    const float* sWhh_b  = (const float*)d_in[16];
    const float* sb_b    = (const float*)d_in[17];
    const float* word_W  = (const float*)d_in[18];
    const float* word_b  = (const float*)d_in[19];
    const float* word_p  = (const float*)d_in[20];
    const float* sent_W  = (const float*)d_in[21];
    const float* sent_b  = (const float*)d_in[22];
    const float* sent_p  = (const float*)d_in[23];
    const float* dense_W = (const float*)d_in[24];
    const float* dense_b = (const float*)d_in[25];
    float* outp = (float*)d_out;

    float *px, *pgpre, *pz, *pscp, *psc, *psenvec, *psx, *pgpre2, *pz2,
          *phT, *pscp2, *psc2, *pdocvec, *pwWt, *psWt, *pwtf, *pwtb, *pstf, *pstb;
    cudaGetSymbolAddress((void**)&px,      d_x);
    cudaGetSymbolAddress((void**)&pgpre,   d_gpre);
    cudaGetSymbolAddress((void**)&pz,      d_z);
    cudaGetSymbolAddress((void**)&pscp,    d_scp);
    cudaGetSymbolAddress((void**)&psc,     d_scores);
    cudaGetSymbolAddress((void**)&psenvec, d_senvec);
    cudaGetSymbolAddress((void**)&psx,     d_sx);
    cudaGetSymbolAddress((void**)&pgpre2,  d_gpre2);
    cudaGetSymbolAddress((void**)&pz2,     d_z2);
    cudaGetSymbolAddress((void**)&phT,     d_hT);
    cudaGetSymbolAddress((void**)&pscp2,   d_scp2);
    cudaGetSymbolAddress((void**)&psc2,    d_scores2);
    cudaGetSymbolAddress((void**)&pdocvec, d_docvec);
    cudaGetSymbolAddress((void**)&pwWt,    d_wWt);
    cudaGetSymbolAddress((void**)&psWt,    d_sWt);
    cudaGetSymbolAddress((void**)&pwtf,    d_wtf);
    cudaGetSymbolAddress((void**)&pwtb,    d_wtb);
    cudaGetSymbolAddress((void**)&pstf,    d_stf);
    cudaGetSymbolAddress((void**)&pstb,    d_stb);

    // dynamic-SMEM caps for scan kernels (idempotent)
    cudaFuncSetAttribute(lstm_scan2<8>, cudaFuncAttributeMaxDynamicSharedMemorySize,
                         2*8*1024*4 + 256*8*4);
    cudaFuncSetAttribute(lstm_scan2<1>, cudaFuncAttributeMaxDynamicSharedMemorySize,
                         2*8*1024*4 + 256*1*4);

    // 1. gather (also fills d_z pos columns)
    gather_x_kernel<<<(M1*DIN1 + 255)/256, 256>>>(tok, wpos, emb, wpe);

    // 2. weight transposes
    transpose_k<<<(Gn*Hn + 255)/256, 256>>>(wWhh_f, pwtf, Gn, Hn);
    transpose_k<<<(Gn*Hn + 255)/256, 256>>>(wWhh_b, pwtb, Gn, Hn);
    transpose_k<<<(Gn*Hn + 255)/256, 256>>>(sWhh_f, pstf, Gn, Hn);
    transpose_k<<<(Gn*Hn + 255)/256, 256>>>(sWhh_b, pstb, Gn, Hn);
    transpose_k<<<(DATT*DATT + 255)/256, 256>>>(word_W, pwWt, DATT, DATT);
    transpose_k<<<(DATT*DATT + 255)/256, 256>>>(sent_W, psWt, DATT, DATT);

    // 3. word input GEMMs
    {
        dim3 g(Gn/128, M1/128);
        gemm_f2<false><<<g, 256>>>(px, wWih_f, wb_f, nullptr, pgpre,               M1, Gn, DIN1);
        gemm_f2<false><<<g, 256>>>(px, wWih_b, wb_b, nullptr, pgpre + (size_t)M1*Gn, M1, Gn, DIN1);
    }

    // 4. word BiLSTM scan -> d_z cols [0,512)
    lstm_scan2<8><<<128, 256, 2*8*1024*4 + 256*8*4>>>(pgpre, pwtf, pwtb, pz,
                                                      nullptr, N1, Ln, DATT);

    // 5. word attention (fused tanh/proj epilogue)
    gemm_f2<true><<<dim3(NBATT, M1/128), 256>>>(pz, pwWt, word_b, word_p, pscp,
                                                M1, DATT, DATT);
    sum_scores<<<(M1 + 255)/256, 256>>>(pscp, psc, M1, NBATT);
    softmax_pool_kernel<<<N1, 256>>>(psc, pz, psenvec, Ln, DATT);

    // 6. sentence input
    build_sx_kernel<<<(N1*DATT + 255)/256, 256>>>(seg, spe);
    fill_z2pos<<<(N1*Pn + 255)/256, 256>>>(seg, spe);
    {
        dim3 g(Gn/128, N1/128);
        gemm_f2<false><<<g, 256>>>(psx, sWih_f, sb_f, nullptr, pgpre2,               N1, Gn, DATT);
        gemm_f2<false><<<g, 256>>>(psx, sWih_b, sb_b, nullptr, pgpre2 + (size_t)N1*Gn, N1, Gn, DATT);
    }

    // 7. sentence BiLSTM scan -> d_z2 cols [0,512), keeps hT
    lstm_scan2<1><<<2*Bn, 256, 2*8*1024*4 + 256*1*4>>>(pgpre2, pstf, pstb, pz2,
                                                       phT, Bn, Sn, DATT);

    // 8. sentence attention
    gemm_f2<true><<<dim3(NBATT, N1/128), 256>>>(pz2, psWt, sent_b, sent_p, pscp2,
                                                N1, DATT, DATT);
    sum_scores<<<(N1 + 255)/256, 256>>>(pscp2, psc2, N1, NBATT);
    softmax_pool_kernel<<<Bn, 256>>>(psc2, pz2, pdocvec, Sn, DATT);

    // 9. classifier head
    final_dense_kernel<<<Bn, 128>>>(dense_W, dense_b, outp);
}